// round 12
// baseline (speedup 1.0000x reference)
#include <cuda_runtime.h>
#include <cstdint>

#define S_DIM 128
#define N_DIM 256
#define CM 256
#define CH 32
#define CZ 128
#define P_DIM 8192
#define LN_EPS 1e-5f
#define OPM_EPS 1e-3f

__device__ __align__(16) float g_a[P_DIM * S_DIM];
__device__ __align__(16) float g_b[P_DIM * S_DIM];
__device__ __align__(16) float g_O[(size_t)P_DIM * P_DIM];
__device__ __align__(16) float g_woT[CZ * CH * CH];
__device__ __align__(16) float g_wpT[64 * CM];
__device__ float g_cw[64];
__device__ float g_c2[64];
__device__ __align__(8) float2 g_stat2[N_DIM * S_DIM];   // [n*128+s] = (r, mu*r)
__device__ float g_norm[N_DIM * N_DIM];

__device__ __forceinline__ uint32_t rna_tf32(float x) {
    uint32_t r;
    asm("cvt.rna.tf32.f32 %0, %1;" : "=r"(r) : "f"(x));
    return r;
}
__device__ __forceinline__ float rnaf(float x) { return __uint_as_float(rna_tf32(x)); }
__device__ __forceinline__ uint32_t smem_u32(const void* p) {
    uint32_t a;
    asm("{ .reg .u64 t; cvta.to.shared.u64 t, %1; cvt.u32.u64 %0, t; }" : "=r"(a) : "l"(p));
    return a;
}
__device__ __forceinline__ void mma_tf32(float* c, const uint32_t* a, const uint32_t* b) {
    asm volatile(
        "mma.sync.aligned.m16n8k8.row.col.f32.tf32.tf32.f32 "
        "{%0,%1,%2,%3}, {%4,%5,%6,%7}, {%8,%9}, {%0,%1,%2,%3};\n"
        : "+f"(c[0]), "+f"(c[1]), "+f"(c[2]), "+f"(c[3])
        : "r"(a[0]), "r"(a[1]), "r"(a[2]), "r"(a[3]), "r"(b[0]), "r"(b[1]));
}
__device__ __forceinline__ void ldsm_x4(uint32_t* r, uint32_t addr) {
    asm volatile("ldmatrix.sync.aligned.m8n8.x4.shared.b16 {%0,%1,%2,%3}, [%4];"
        : "=r"(r[0]), "=r"(r[1]), "=r"(r[2]), "=r"(r[3]) : "r"(addr));
}
__device__ __forceinline__ void cp16(uint32_t d, const float* s) {
    asm volatile("cp.async.cg.shared.global [%0], [%1], 16;" :: "r"(d), "l"(s));
}
__device__ __forceinline__ void cp16_ca(uint32_t d, const float* s) {
    asm volatile("cp.async.ca.shared.global [%0], [%1], 16;" :: "r"(d), "l"(s));
}
#define CP_COMMIT() asm volatile("cp.async.commit_group;" ::: "memory")
#define CP_WAIT1()  asm volatile("cp.async.wait_group 1;" ::: "memory")

#define ROW_BYTES   144u
#define STAGE_BYTES 36864u
#define B_OFF       18432u
#define SMEM_BYTES  (3 * 36864)
#define PSTG_FL     6912
#define PB_FL       4608
#define PSMEM2      (2 * 27648 + 1024)

__device__ __forceinline__ void mma_chunk(uint32_t a_base, uint32_t b_base,
                                          float acc[4][4][4]) {
    #pragma unroll
    for (int kk = 0; kk < 4; kk++) {
        uint32_t af[4][4], bf[4][2];
        #pragma unroll
        for (int mt = 0; mt < 4; mt++)
            ldsm_x4(af[mt], a_base + kk * 32 + mt * (16 * ROW_BYTES));
        #pragma unroll
        for (int pr = 0; pr < 2; pr++) {
            uint32_t t[4];
            ldsm_x4(t, b_base + kk * 32 + pr * (16 * ROW_BYTES));
            bf[2 * pr][0] = t[0]; bf[2 * pr][1] = t[1];
            bf[2 * pr + 1][0] = t[2]; bf[2 * pr + 1][1] = t[3];
        }
        #pragma unroll
        for (int mt = 0; mt < 4; mt++)
            #pragma unroll
            for (int nt = 0; nt < 4; nt++)
                mma_tf32(acc[mt][nt], af[mt], bf[nt]);
    }
}

__global__ void __launch_bounds__(256) stats_kernel(const float* __restrict__ m) {
    const int row = blockIdx.x * 8 + (threadIdx.x >> 5);
    const int lane = threadIdx.x & 31;
    const float* src = m + (size_t)row * CM;
    float4 v0 = *(const float4*)&src[lane * 4];
    float4 v1 = *(const float4*)&src[128 + lane * 4];
    float s1 = v0.x + v0.y + v0.z + v0.w + v1.x + v1.y + v1.z + v1.w;
    float s2 = v0.x*v0.x + v0.y*v0.y + v0.z*v0.z + v0.w*v0.w
             + v1.x*v1.x + v1.y*v1.y + v1.z*v1.z + v1.w*v1.w;
    #pragma unroll
    for (int o = 16; o > 0; o >>= 1) {
        s1 += __shfl_xor_sync(0xffffffff, s1, o);
        s2 += __shfl_xor_sync(0xffffffff, s2, o);
    }
    if (lane == 0) {
        float mu = s1 * (1.f / CM);
        float var = s2 * (1.f / CM) - mu * mu;
        float r = rsqrtf(var + LN_EPS);
        const int s = row >> 8, n = row & 255;
        g_stat2[n * S_DIM + s] = make_float2(r, mu * r);
    }
}

__global__ void __launch_bounds__(256) prep_kernel(
        const float* __restrict__ w1, const float* __restrict__ b1,
        const float* __restrict__ w2, const float* __restrict__ b2,
        const float* __restrict__ ln_w, const float* __restrict__ ln_b) {
    const int h = threadIdx.x & 63, kq = threadIdx.x >> 6;
    const float* w = (h < 32) ? w1 : w2;
    const int hh = h & 31;
    float cw = 0.f, cb = 0.f;
    for (int k = kq * 64; k < kq * 64 + 64; k++) {
        float v = ln_w[k] * w[k * CH + hh];
        float rv = rnaf(v);
        g_wpT[h * CM + k] = rv;
        cw += rv;
        cb += ln_b[k] * w[k * CH + hh];
    }
    __shared__ float scw[4][64], scb[4][64];
    scw[kq][h] = cw; scb[kq][h] = cb;
    __syncthreads();
    if (kq == 0) {
        g_cw[h] = scw[0][h] + scw[1][h] + scw[2][h] + scw[3][h];
        float tb = scb[0][h] + scb[1][h] + scb[2][h] + scb[3][h];
        g_c2[h] = tb + ((h < 32) ? b1[h] : b2[hh]);
    }
}

// proj_mma: rna(m) @ W' per n-CTA; A via LDG+rna+STS double-buffer (no g_mr).
__global__ void __launch_bounds__(128) proj_mma(const float* __restrict__ m,
                                                const float* __restrict__ mask) {
    extern __shared__ __align__(16) float sm[];
    float2* sstat = (float2*)&sm[2 * PSTG_FL];
    const uint32_t sbase = smem_u32(sm);
    const int tid = threadIdx.x, wid = tid >> 5, lane = tid & 31;
    const int wm = (wid & 1) * 64, wn = (wid >> 1) * 32;
    const int n = blockIdx.x;
    const int lg = lane >> 3, lrow = lane & 7;
    const uint32_t a_lo = (uint32_t)(wm + (lg & 1) * 8 + lrow) * ROW_BYTES
                        + (uint32_t)(lg >> 1) * 16;
    const uint32_t b_lo = PB_FL * 4u + (uint32_t)(wn + (lg >> 1) * 8 + lrow) * ROW_BYTES
                        + (uint32_t)(lg & 1) * 16;
    const int rbase = tid >> 3, cc = tid & 7;

    // stage stats into smem (coalesced 128 float2)
    if (tid < 128) sstat[tid] = g_stat2[n * S_DIM + tid];

    float acc[4][4][4];
    #pragma unroll
    for (int a = 0; a < 4; a++)
        #pragma unroll
        for (int b = 0; b < 4; b++)
            #pragma unroll
            for (int e = 0; e < 4; e++) acc[a][b][e] = 0.f;

    float4 pa[8], pb[4];

    auto load_regs = [&](int ch) {
        const int kb = ch * 32;
        #pragma unroll
        for (int i = 0; i < 8; i++) {
            const int rr = rbase + i * 16;
            pa[i] = *(const float4*)&m[((size_t)rr * N_DIM + n) * CM + kb + cc * 4];
        }
        #pragma unroll
        for (int i = 0; i < 4; i++) {
            const int f = tid + i * 128, rr = f >> 3, c8 = f & 7;
            pb[i] = *(const float4*)&g_wpT[rr * CM + kb + c8 * 4];
        }
    };
    auto sts_regs = [&](int buf) {
        float* A = &sm[buf * PSTG_FL];
        float* B = A + PB_FL;
        #pragma unroll
        for (int i = 0; i < 8; i++) {
            const int rr = rbase + i * 16;
            float4 v;
            v.x = rnaf(pa[i].x); v.y = rnaf(pa[i].y);
            v.z = rnaf(pa[i].z); v.w = rnaf(pa[i].w);
            *(float4*)&A[rr * 36 + cc * 4] = v;
        }
        #pragma unroll
        for (int i = 0; i < 4; i++) {
            const int f = tid + i * 128, rr = f >> 3, c8 = f & 7;
            *(float4*)&B[rr * 36 + c8 * 4] = pb[i];
        }
    };

    load_regs(0);
    sts_regs(0);
    __syncthreads();

    #pragma unroll 1
    for (int ch = 0; ch < 8; ch++) {
        if (ch < 7) load_regs(ch + 1);
        const uint32_t so = sbase + (uint32_t)(ch & 1) * (PSTG_FL * 4u);
        mma_chunk(so + a_lo, so + b_lo, acc);
        if (ch < 7) {
            sts_regs((ch + 1) & 1);
            __syncthreads();
        }
    }

    float* dst = (wn == 0) ? g_a : g_b;
    #pragma unroll
    for (int mt = 0; mt < 4; mt++) {
        const int s0 = wm + mt * 16 + (lane >> 2);
        const float2 st0 = sstat[s0];
        const float2 st1 = sstat[s0 + 8];
        const float mk0 = mask[s0 * N_DIM + n];
        const float mk1 = mask[(s0 + 8) * N_DIM + n];
        #pragma unroll
        for (int nt = 0; nt < 4; nt++) {
            const int h = wn + nt * 8 + (lane & 3) * 2;
            const int hh = h & 31;
            const float cwa = g_cw[h], cwb = g_cw[h + 1];
            const float c2a = g_c2[h], c2b = g_c2[h + 1];
            float* d0 = &dst[(size_t)(n * CH + hh) * S_DIM];
            float* d1 = d0 + S_DIM;
            d0[s0]     = rnaf((st0.x * acc[mt][nt][0] - st0.y * cwa + c2a) * mk0);
            d1[s0]     = rnaf((st0.x * acc[mt][nt][1] - st0.y * cwb + c2b) * mk0);
            d0[s0 + 8] = rnaf((st1.x * acc[mt][nt][2] - st1.y * cwa + c2a) * mk1);
            d1[s0 + 8] = rnaf((st1.x * acc[mt][nt][3] - st1.y * cwb + c2b) * mk1);
        }
    }
}

__global__ void norm_kernel(const float* __restrict__ mask) {
    const int i = blockIdx.x, j = threadIdx.x;
    __shared__ float mi[S_DIM];
    if (j < S_DIM) mi[j] = mask[j * N_DIM + i];
    __syncthreads();
    float acc = 0.f;
    #pragma unroll 8
    for (int s = 0; s < S_DIM; s++) acc += mi[s] * mask[s * N_DIM + j];
    g_norm[i * N_DIM + j] = acc + OPM_EPS;
}

__global__ void __launch_bounds__(256) woT_kernel(const float* __restrict__ wo) {
    __shared__ float t[32][33];
    const int kb = blockIdx.x * 32, zb = blockIdx.y * 32;
    const int tx = threadIdx.x & 31, ty = threadIdx.x >> 5;
    #pragma unroll
    for (int r = 0; r < 32; r += 8)
        t[ty + r][tx] = wo[(size_t)(kb + ty + r) * CZ + zb + tx];
    __syncthreads();
    #pragma unroll
    for (int r = 0; r < 32; r += 8)
        g_woT[(size_t)(zb + ty + r) * 1024 + kb + tx] = rnaf(t[tx][ty + r]);
}

__global__ void __launch_bounds__(256, 2) gemm1_mma() {
    extern __shared__ __align__(16) float sm[];
    const uint32_t sbase = smem_u32(sm);
    const int tid = threadIdx.x, wid = tid >> 5, lane = tid & 31;
    const int wm = (wid & 1) * 64, wn = (wid >> 1) * 32;
    const int p0 = blockIdx.y * 128, q0 = blockIdx.x * 128;
    const int lg = lane >> 3, lrow = lane & 7;
    const uint32_t a_lo = (uint32_t)(wm + (lg & 1) * 8 + lrow) * ROW_BYTES
                        + (uint32_t)(lg >> 1) * 16;
    const uint32_t b_lo = B_OFF + (uint32_t)(wn + (lg >> 1) * 8 + lrow) * ROW_BYTES
                        + (uint32_t)(lg & 1) * 16;

    float acc[4][4][4];
    #pragma unroll
    for (int a = 0; a < 4; a++)
        #pragma unroll
        for (int b = 0; b < 4; b++)
            #pragma unroll
            for (int e = 0; e < 4; e++) acc[a][b][e] = 0.f;

    auto copy1 = [&](int ch, int st) {
        const int kb = ch * 32;
        const uint32_t dA = sbase + st * STAGE_BYTES;
        const uint32_t dB = dA + B_OFF;
        #pragma unroll
        for (int i = 0; i < 4; i++) {
            int f = tid + i * 256, rr = f >> 3, cc = f & 7;
            cp16(dA + rr * ROW_BYTES + cc * 16,
                 &g_a[(size_t)(p0 + rr) * S_DIM + kb + cc * 4]);
            cp16(dB + rr * ROW_BYTES + cc * 16,
                 &g_b[(size_t)(q0 + rr) * S_DIM + kb + cc * 4]);
        }
    };

    copy1(0, 0); CP_COMMIT();
    copy1(1, 1); CP_COMMIT();

    #pragma unroll
    for (int ch = 0; ch < 4; ch++) {
        CP_WAIT1();
        __syncthreads();
        const uint32_t so = sbase + (uint32_t)(ch % 3) * STAGE_BYTES;
        mma_chunk(so + a_lo, so + b_lo, acc);
        if (ch + 2 < 4) copy1(ch + 2, (ch + 2) % 3);
        CP_COMMIT();
    }

    #pragma unroll
    for (int mt = 0; mt < 4; mt++) {
        const int row0 = p0 + wm + mt * 16 + (lane >> 2);
        #pragma unroll
        for (int nt = 0; nt < 4; nt++) {
            const int col = q0 + wn + nt * 8 + (lane & 3) * 2;
            float2 v0, v1;
            v0.x = rnaf(acc[mt][nt][0]); v0.y = rnaf(acc[mt][nt][1]);
            v1.x = rnaf(acc[mt][nt][2]); v1.y = rnaf(acc[mt][nt][3]);
            *(float2*)&g_O[(size_t)row0 * P_DIM + col]       = v0;
            *(float2*)&g_O[(size_t)(row0 + 8) * P_DIM + col] = v1;
        }
    }
}

__global__ void __launch_bounds__(256, 2) gemm2_mma(const float* __restrict__ bo,
                                                    float* __restrict__ out) {
    extern __shared__ __align__(16) float sm[];
    const uint32_t sbase = smem_u32(sm);
    const int tid = threadIdx.x, wid = tid >> 5, lane = tid & 31;
    const int wm = (wid & 1) * 64, wn = (wid >> 1) * 32;
    const int m0 = blockIdx.x * 128;
    const int i_idx = m0 >> 8, j0 = m0 & 255;
    const int lg = lane >> 3, lrow = lane & 7;
    const uint32_t a_lo = (uint32_t)(wm + (lg & 1) * 8 + lrow) * ROW_BYTES
                        + (uint32_t)(lg >> 1) * 16;
    const uint32_t b_lo = B_OFF + (uint32_t)(wn + (lg >> 1) * 8 + lrow) * ROW_BYTES
                        + (uint32_t)(lg & 1) * 16;

    float acc[4][4][4];
    #pragma unroll
    for (int a = 0; a < 4; a++)
        #pragma unroll
        for (int b = 0; b < 4; b++)
            #pragma unroll
            for (int e = 0; e < 4; e++) acc[a][b][e] = 0.f;

    auto copy1 = [&](int ch, int st) {
        const float* gA = &g_O[((size_t)(i_idx * 32 + ch)) * P_DIM + (size_t)j0 * 32];
        const uint32_t dA = sbase + st * STAGE_BYTES;
        const uint32_t dB = dA + B_OFF;
        #pragma unroll
        for (int i = 0; i < 4; i++) {
            int f = tid + i * 256, rr = f >> 3, cc = f & 7;
            cp16(dA + rr * ROW_BYTES + cc * 16, &gA[f * 4]);
            cp16_ca(dB + rr * ROW_BYTES + cc * 16,
                    &g_woT[(size_t)rr * 1024 + ch * 32 + cc * 4]);
        }
    };

    copy1(0, 0); CP_COMMIT();
    copy1(1, 1); CP_COMMIT();

    int st = 0;
    for (int ch = 0; ch < 32; ch++) {
        CP_WAIT1();
        __syncthreads();
        const uint32_t so = sbase + (uint32_t)st * STAGE_BYTES;
        mma_chunk(so + a_lo, so + b_lo, acc);
        if (ch + 2 < 32) {
            int ns = st + 2; if (ns >= 3) ns -= 3;
            copy1(ch + 2, ns);
        }
        CP_COMMIT();
        if (++st == 3) st = 0;
    }

    #pragma unroll
    for (int mt = 0; mt < 4; mt++) {
        const int row0 = m0 + wm + mt * 16 + (lane >> 2);
        const float inv0 = 1.0f / g_norm[row0];
        const float inv1 = 1.0f / g_norm[row0 + 8];
        #pragma unroll
        for (int nt = 0; nt < 4; nt++) {
            const int col = wn + nt * 8 + (lane & 3) * 2;
            const float b0v = bo[col], b1v = bo[col + 1];
            float2 v0, v1;
            v0.x = (acc[mt][nt][0] + b0v) * inv0;
            v0.y = (acc[mt][nt][1] + b1v) * inv0;
            v1.x = (acc[mt][nt][2] + b0v) * inv1;
            v1.y = (acc[mt][nt][3] + b1v) * inv1;
            *(float2*)&out[(size_t)row0 * CZ + col]       = v0;
            *(float2*)&out[(size_t)(row0 + 8) * CZ + col] = v1;
        }
    }
}

extern "C" void kernel_launch(void* const* d_in, const int* in_sizes, int n_in,
                              void* d_out, int out_size) {
    const float* m    = (const float*)d_in[0];
    const float* mask = (const float*)d_in[1];
    const float* ln_w = (const float*)d_in[2];
    const float* ln_b = (const float*)d_in[3];
    const float* w1   = (const float*)d_in[4];
    const float* b1   = (const float*)d_in[5];
    const float* w2   = (const float*)d_in[6];
    const float* b2   = (const float*)d_in[7];
    const float* wo   = (const float*)d_in[8];
    const float* bo   = (const float*)d_in[9];
    float* out = (float*)d_out;

    cudaFuncSetAttribute(proj_mma, cudaFuncAttributeMaxDynamicSharedMemorySize, PSMEM2);
    cudaFuncSetAttribute(gemm1_mma, cudaFuncAttributeMaxDynamicSharedMemorySize, SMEM_BYTES);
    cudaFuncSetAttribute(gemm2_mma, cudaFuncAttributeMaxDynamicSharedMemorySize, SMEM_BYTES);

    stats_kernel<<<4096, 256>>>(m);
    prep_kernel<<<1, 256>>>(w1, b1, w2, b2, ln_w, ln_b);
    norm_kernel<<<N_DIM, 256>>>(mask);
    woT_kernel<<<dim3(32, 4), 256>>>(wo);

    proj_mma<<<256, 128, PSMEM2>>>(m, mask);

    dim3 g1(64, 64);
    gemm1_mma<<<g1, 256, SMEM_BYTES>>>();
    gemm2_mma<<<512, 256, SMEM_BYTES>>>(bo, out);
}

// round 13
// speedup vs baseline: 1.0408x; 1.0408x over previous
#include <cuda_runtime.h>
#include <cstdint>

#define S_DIM 128
#define N_DIM 256
#define CM 256
#define CH 32
#define CZ 128
#define P_DIM 8192
#define LN_EPS 1e-5f
#define OPM_EPS 1e-3f

__device__ __align__(16) float g_a[P_DIM * S_DIM];
__device__ __align__(16) float g_b[P_DIM * S_DIM];
__device__ __align__(16) float g_O[(size_t)P_DIM * P_DIM];
__device__ __align__(16) float g_woT[CZ * CH * CH];
__device__ __align__(16) float g_wpT[64 * CM];
__device__ float g_cw[64];
__device__ float g_c2[64];
__device__ float g_norm[N_DIM * N_DIM];

__device__ __forceinline__ uint32_t rna_tf32(float x) {
    uint32_t r;
    asm("cvt.rna.tf32.f32 %0, %1;" : "=r"(r) : "f"(x));
    return r;
}
__device__ __forceinline__ float rnaf(float x) { return __uint_as_float(rna_tf32(x)); }
__device__ __forceinline__ uint32_t smem_u32(const void* p) {
    uint32_t a;
    asm("{ .reg .u64 t; cvta.to.shared.u64 t, %1; cvt.u32.u64 %0, t; }" : "=r"(a) : "l"(p));
    return a;
}
__device__ __forceinline__ void mma_tf32(float* c, const uint32_t* a, const uint32_t* b) {
    asm volatile(
        "mma.sync.aligned.m16n8k8.row.col.f32.tf32.tf32.f32 "
        "{%0,%1,%2,%3}, {%4,%5,%6,%7}, {%8,%9}, {%0,%1,%2,%3};\n"
        : "+f"(c[0]), "+f"(c[1]), "+f"(c[2]), "+f"(c[3])
        : "r"(a[0]), "r"(a[1]), "r"(a[2]), "r"(a[3]), "r"(b[0]), "r"(b[1]));
}
__device__ __forceinline__ void ldsm_x4(uint32_t* r, uint32_t addr) {
    asm volatile("ldmatrix.sync.aligned.m8n8.x4.shared.b16 {%0,%1,%2,%3}, [%4];"
        : "=r"(r[0]), "=r"(r[1]), "=r"(r[2]), "=r"(r[3]) : "r"(addr));
}
__device__ __forceinline__ void cp16(uint32_t d, const float* s) {
    asm volatile("cp.async.cg.shared.global [%0], [%1], 16;" :: "r"(d), "l"(s));
}
__device__ __forceinline__ void cp16_ca(uint32_t d, const float* s) {
    asm volatile("cp.async.ca.shared.global [%0], [%1], 16;" :: "r"(d), "l"(s));
}
#define CP_COMMIT() asm volatile("cp.async.commit_group;" ::: "memory")
#define CP_WAIT1()  asm volatile("cp.async.wait_group 1;" ::: "memory")

#define ROW_BYTES   144u
#define STAGE_BYTES 36864u
#define B_OFF       18432u
#define SMEM_BYTES  (3 * 36864)
#define PSTG_FL     6912
#define PB_FL       4608
#define PSMEM2      (2 * 27648 + 1024)

__device__ __forceinline__ void mma_chunk(uint32_t a_base, uint32_t b_base,
                                          float acc[4][4][4]) {
    #pragma unroll
    for (int kk = 0; kk < 4; kk++) {
        uint32_t af[4][4], bf[4][2];
        #pragma unroll
        for (int mt = 0; mt < 4; mt++)
            ldsm_x4(af[mt], a_base + kk * 32 + mt * (16 * ROW_BYTES));
        #pragma unroll
        for (int pr = 0; pr < 2; pr++) {
            uint32_t t[4];
            ldsm_x4(t, b_base + kk * 32 + pr * (16 * ROW_BYTES));
            bf[2 * pr][0] = t[0]; bf[2 * pr][1] = t[1];
            bf[2 * pr + 1][0] = t[2]; bf[2 * pr + 1][1] = t[3];
        }
        #pragma unroll
        for (int mt = 0; mt < 4; mt++)
            #pragma unroll
            for (int nt = 0; nt < 4; nt++)
                mma_tf32(acc[mt][nt], af[mt], bf[nt]);
    }
}

// ============================================================================
// setup kernel: block 0 = prep (wpT/cw/c2); blocks 1..256 = norm;
// blocks 257..384 = woT transpose.  One launch replaces three.
// ============================================================================
__global__ void __launch_bounds__(256) setup_kernel(
        const float* __restrict__ mask,
        const float* __restrict__ wo,
        const float* __restrict__ w1, const float* __restrict__ b1,
        const float* __restrict__ w2, const float* __restrict__ b2,
        const float* __restrict__ ln_w, const float* __restrict__ ln_b) {
    const int bid = blockIdx.x;
    if (bid == 0) {
        // prep
        const int h = threadIdx.x & 63, kq = threadIdx.x >> 6;
        const float* w = (h < 32) ? w1 : w2;
        const int hh = h & 31;
        float cw = 0.f, cb = 0.f;
        for (int k = kq * 64; k < kq * 64 + 64; k++) {
            float v = ln_w[k] * w[k * CH + hh];
            float rv = rnaf(v);
            g_wpT[h * CM + k] = rv;
            cw += rv;
            cb += ln_b[k] * w[k * CH + hh];
        }
        __shared__ float scw[4][64], scb[4][64];
        scw[kq][h] = cw; scb[kq][h] = cb;
        __syncthreads();
        if (kq == 0) {
            g_cw[h] = scw[0][h] + scw[1][h] + scw[2][h] + scw[3][h];
            float tb = scb[0][h] + scb[1][h] + scb[2][h] + scb[3][h];
            g_c2[h] = tb + ((h < 32) ? b1[h] : b2[hh]);
        }
    } else if (bid <= 256) {
        // norm row i
        const int i = bid - 1, j = threadIdx.x;
        __shared__ float mi[S_DIM];
        if (j < S_DIM) mi[j] = mask[j * N_DIM + i];
        __syncthreads();
        float acc = 0.f;
        #pragma unroll 8
        for (int s = 0; s < S_DIM; s++) acc += mi[s] * mask[s * N_DIM + j];
        g_norm[i * N_DIM + j] = acc + OPM_EPS;
    } else {
        // woT transpose tile
        const int t = bid - 257;                 // 0..127
        __shared__ float tt[32][33];
        const int kb = (t & 31) * 32, zb = (t >> 5) * 32;
        const int tx = threadIdx.x & 31, ty = threadIdx.x >> 5;
        #pragma unroll
        for (int r = 0; r < 32; r += 8)
            tt[ty + r][tx] = wo[(size_t)(kb + ty + r) * CZ + zb + tx];
        __syncthreads();
        #pragma unroll
        for (int r = 0; r < 32; r += 8)
            g_woT[(size_t)(zb + ty + r) * 1024 + kb + tx] = rnaf(tt[tx][ty + r]);
    }
}

// ============================================================================
// proj_mma: rna(m) @ W' per n-CTA, LayerNorm stats computed INLINE.
// Each thread owns 8 rows (rbase + i*16) x its cc k-slice; per-row partials
// reduced over the 8 cc-lanes after the mainloop.
// ============================================================================
__global__ void __launch_bounds__(128) proj_mma(const float* __restrict__ m,
                                                const float* __restrict__ mask) {
    extern __shared__ __align__(16) float sm[];
    float2* sstat = (float2*)&sm[2 * PSTG_FL];     // [128] = (r, mu*r)
    const uint32_t sbase = smem_u32(sm);
    const int tid = threadIdx.x, wid = tid >> 5, lane = tid & 31;
    const int wm = (wid & 1) * 64, wn = (wid >> 1) * 32;
    const int n = blockIdx.x;
    const int lg = lane >> 3, lrow = lane & 7;
    const uint32_t a_lo = (uint32_t)(wm + (lg & 1) * 8 + lrow) * ROW_BYTES
                        + (uint32_t)(lg >> 1) * 16;
    const uint32_t b_lo = PB_FL * 4u + (uint32_t)(wn + (lg >> 1) * 8 + lrow) * ROW_BYTES
                        + (uint32_t)(lg & 1) * 16;
    const int rbase = tid >> 3, cc = tid & 7;

    float acc[4][4][4];
    #pragma unroll
    for (int a = 0; a < 4; a++)
        #pragma unroll
        for (int b = 0; b < 4; b++)
            #pragma unroll
            for (int e = 0; e < 4; e++) acc[a][b][e] = 0.f;

    float4 pa[8], pb[4];
    float s1p[8], s2p[8];
    #pragma unroll
    for (int i = 0; i < 8; i++) { s1p[i] = 0.f; s2p[i] = 0.f; }

    auto load_regs = [&](int ch) {
        const int kb = ch * 32;
        #pragma unroll
        for (int i = 0; i < 8; i++) {
            const int rr = rbase + i * 16;
            pa[i] = *(const float4*)&m[((size_t)rr * N_DIM + n) * CM + kb + cc * 4];
            s1p[i] += pa[i].x + pa[i].y + pa[i].z + pa[i].w;
            s2p[i] += pa[i].x * pa[i].x + pa[i].y * pa[i].y
                    + pa[i].z * pa[i].z + pa[i].w * pa[i].w;
        }
        #pragma unroll
        for (int i = 0; i < 4; i++) {
            const int f = tid + i * 128, rr = f >> 3, c8 = f & 7;
            pb[i] = *(const float4*)&g_wpT[rr * CM + kb + c8 * 4];
        }
    };
    auto sts_regs = [&](int buf) {
        float* A = &sm[buf * PSTG_FL];
        float* B = A + PB_FL;
        #pragma unroll
        for (int i = 0; i < 8; i++) {
            const int rr = rbase + i * 16;
            float4 v;
            v.x = rnaf(pa[i].x); v.y = rnaf(pa[i].y);
            v.z = rnaf(pa[i].z); v.w = rnaf(pa[i].w);
            *(float4*)&A[rr * 36 + cc * 4] = v;
        }
        #pragma unroll
        for (int i = 0; i < 4; i++) {
            const int f = tid + i * 128, rr = f >> 3, c8 = f & 7;
            *(float4*)&B[rr * 36 + c8 * 4] = pb[i];
        }
    };

    load_regs(0);
    sts_regs(0);
    __syncthreads();

    #pragma unroll 1
    for (int ch = 0; ch < 8; ch++) {
        if (ch < 7) load_regs(ch + 1);
        const uint32_t so = sbase + (uint32_t)(ch & 1) * (PSTG_FL * 4u);
        mma_chunk(so + a_lo, so + b_lo, acc);
        if (ch < 7) {
            sts_regs((ch + 1) & 1);
            __syncthreads();
        }
    }

    // finish stats: per-row reduce across the 8 cc-lanes sharing rbase
    #pragma unroll
    for (int i = 0; i < 8; i++) {
        float a = s1p[i], b = s2p[i];
        #pragma unroll
        for (int o = 1; o < 8; o <<= 1) {
            a += __shfl_xor_sync(0xffffffff, a, o);
            b += __shfl_xor_sync(0xffffffff, b, o);
        }
        if (cc == 0) {
            const int row = rbase + i * 16;
            float mu = a * (1.f / CM);
            float var = b * (1.f / CM) - mu * mu;
            float r = rsqrtf(var + LN_EPS);
            sstat[row] = make_float2(r, mu * r);
        }
    }
    __syncthreads();

    float* dst = (wn == 0) ? g_a : g_b;
    #pragma unroll
    for (int mt = 0; mt < 4; mt++) {
        const int s0 = wm + mt * 16 + (lane >> 2);
        const float2 st0 = sstat[s0];
        const float2 st1 = sstat[s0 + 8];
        const float mk0 = mask[s0 * N_DIM + n];
        const float mk1 = mask[(s0 + 8) * N_DIM + n];
        #pragma unroll
        for (int nt = 0; nt < 4; nt++) {
            const int h = wn + nt * 8 + (lane & 3) * 2;
            const int hh = h & 31;
            const float cwa = g_cw[h], cwb = g_cw[h + 1];
            const float c2a = g_c2[h], c2b = g_c2[h + 1];
            float* d0 = &dst[(size_t)(n * CH + hh) * S_DIM];
            float* d1 = d0 + S_DIM;
            d0[s0]     = rnaf((st0.x * acc[mt][nt][0] - st0.y * cwa + c2a) * mk0);
            d1[s0]     = rnaf((st0.x * acc[mt][nt][1] - st0.y * cwb + c2b) * mk0);
            d0[s0 + 8] = rnaf((st1.x * acc[mt][nt][2] - st1.y * cwa + c2a) * mk1);
            d1[s0 + 8] = rnaf((st1.x * acc[mt][nt][3] - st1.y * cwb + c2b) * mk1);
        }
    }
}

// ============================================================================
// GEMM1: O[8192,8192] = A[8192,128]*B[8192,128]^T.  128x128 CTA, 8 warps
// (2M x 4N) of 64x32, cp.async 3-stage pipeline, NC=4 chunks, 2 CTAs/SM.
// ============================================================================
__global__ void __launch_bounds__(256, 2) gemm1_mma() {
    extern __shared__ __align__(16) float sm[];
    const uint32_t sbase = smem_u32(sm);
    const int tid = threadIdx.x, wid = tid >> 5, lane = tid & 31;
    const int wm = (wid & 1) * 64, wn = (wid >> 1) * 32;
    const int p0 = blockIdx.y * 128, q0 = blockIdx.x * 128;
    const int lg = lane >> 3, lrow = lane & 7;
    const uint32_t a_lo = (uint32_t)(wm + (lg & 1) * 8 + lrow) * ROW_BYTES
                        + (uint32_t)(lg >> 1) * 16;
    const uint32_t b_lo = B_OFF + (uint32_t)(wn + (lg >> 1) * 8 + lrow) * ROW_BYTES
                        + (uint32_t)(lg & 1) * 16;

    float acc[4][4][4];
    #pragma unroll
    for (int a = 0; a < 4; a++)
        #pragma unroll
        for (int b = 0; b < 4; b++)
            #pragma unroll
            for (int e = 0; e < 4; e++) acc[a][b][e] = 0.f;

    auto copy1 = [&](int ch, int st) {
        const int kb = ch * 32;
        const uint32_t dA = sbase + st * STAGE_BYTES;
        const uint32_t dB = dA + B_OFF;
        #pragma unroll
        for (int i = 0; i < 4; i++) {
            int f = tid + i * 256, rr = f >> 3, cc = f & 7;
            cp16(dA + rr * ROW_BYTES + cc * 16,
                 &g_a[(size_t)(p0 + rr) * S_DIM + kb + cc * 4]);
            cp16(dB + rr * ROW_BYTES + cc * 16,
                 &g_b[(size_t)(q0 + rr) * S_DIM + kb + cc * 4]);
        }
    };

    copy1(0, 0); CP_COMMIT();
    copy1(1, 1); CP_COMMIT();

    #pragma unroll
    for (int ch = 0; ch < 4; ch++) {
        CP_WAIT1();
        __syncthreads();
        const uint32_t so = sbase + (uint32_t)(ch % 3) * STAGE_BYTES;
        mma_chunk(so + a_lo, so + b_lo, acc);
        if (ch + 2 < 4) copy1(ch + 2, (ch + 2) % 3);
        CP_COMMIT();
    }

    #pragma unroll
    for (int mt = 0; mt < 4; mt++) {
        const int row0 = p0 + wm + mt * 16 + (lane >> 2);
        #pragma unroll
        for (int nt = 0; nt < 4; nt++) {
            const int col = q0 + wn + nt * 8 + (lane & 3) * 2;
            float2 v0, v1;
            v0.x = rnaf(acc[mt][nt][0]); v0.y = rnaf(acc[mt][nt][1]);
            v1.x = rnaf(acc[mt][nt][2]); v1.y = rnaf(acc[mt][nt][3]);
            *(float2*)&g_O[(size_t)row0 * P_DIM + col]       = v0;
            *(float2*)&g_O[(size_t)(row0 + 8) * P_DIM + col] = v1;
        }
    }
}

// ============================================================================
// GEMM2: out[65536,128] = O'[65536,1024] @ woT^T (+bo, /norm).
// 128x128 CTA, 8 warps (2M x 4N) of 64x32, cp.async 3-stage, NC=32 chunks.
// ============================================================================
__global__ void __launch_bounds__(256, 2) gemm2_mma(const float* __restrict__ bo,
                                                    float* __restrict__ out) {
    extern __shared__ __align__(16) float sm[];
    const uint32_t sbase = smem_u32(sm);
    const int tid = threadIdx.x, wid = tid >> 5, lane = tid & 31;
    const int wm = (wid & 1) * 64, wn = (wid >> 1) * 32;
    const int m0 = blockIdx.x * 128;
    const int i_idx = m0 >> 8, j0 = m0 & 255;
    const int lg = lane >> 3, lrow = lane & 7;
    const uint32_t a_lo = (uint32_t)(wm + (lg & 1) * 8 + lrow) * ROW_BYTES
                        + (uint32_t)(lg >> 1) * 16;
    const uint32_t b_lo = B_OFF + (uint32_t)(wn + (lg >> 1) * 8 + lrow) * ROW_BYTES
                        + (uint32_t)(lg & 1) * 16;

    float acc[4][4][4];
    #pragma unroll
    for (int a = 0; a < 4; a++)
        #pragma unroll
        for (int b = 0; b < 4; b++)
            #pragma unroll
            for (int e = 0; e < 4; e++) acc[a][b][e] = 0.f;

    auto copy1 = [&](int ch, int st) {
        const float* gA = &g_O[((size_t)(i_idx * 32 + ch)) * P_DIM + (size_t)j0 * 32];
        const uint32_t dA = sbase + st * STAGE_BYTES;
        const uint32_t dB = dA + B_OFF;
        #pragma unroll
        for (int i = 0; i < 4; i++) {
            int f = tid + i * 256, rr = f >> 3, cc = f & 7;
            cp16(dA + rr * ROW_BYTES + cc * 16, &gA[f * 4]);
            cp16_ca(dB + rr * ROW_BYTES + cc * 16,
                    &g_woT[(size_t)rr * 1024 + ch * 32 + cc * 4]);
        }
    };

    copy1(0, 0); CP_COMMIT();
    copy1(1, 1); CP_COMMIT();

    int st = 0;
    for (int ch = 0; ch < 32; ch++) {
        CP_WAIT1();
        __syncthreads();
        const uint32_t so = sbase + (uint32_t)st * STAGE_BYTES;
        mma_chunk(so + a_lo, so + b_lo, acc);
        if (ch + 2 < 32) {
            int ns = st + 2; if (ns >= 3) ns -= 3;
            copy1(ch + 2, ns);
        }
        CP_COMMIT();
        if (++st == 3) st = 0;
    }

    #pragma unroll
    for (int mt = 0; mt < 4; mt++) {
        const int row0 = m0 + wm + mt * 16 + (lane >> 2);
        const float inv0 = 1.0f / g_norm[row0];
        const float inv1 = 1.0f / g_norm[row0 + 8];
        #pragma unroll
        for (int nt = 0; nt < 4; nt++) {
            const int col = wn + nt * 8 + (lane & 3) * 2;
            const float b0v = bo[col], b1v = bo[col + 1];
            float2 v0, v1;
            v0.x = (acc[mt][nt][0] + b0v) * inv0;
            v0.y = (acc[mt][nt][1] + b1v) * inv0;
            v1.x = (acc[mt][nt][2] + b0v) * inv1;
            v1.y = (acc[mt][nt][3] + b1v) * inv1;
            *(float2*)&out[(size_t)row0 * CZ + col]       = v0;
            *(float2*)&out[(size_t)(row0 + 8) * CZ + col] = v1;
        }
    }
}

extern "C" void kernel_launch(void* const* d_in, const int* in_sizes, int n_in,
                              void* d_out, int out_size) {
    const float* m    = (const float*)d_in[0];
    const float* mask = (const float*)d_in[1];
    const float* ln_w = (const float*)d_in[2];
    const float* ln_b = (const float*)d_in[3];
    const float* w1   = (const float*)d_in[4];
    const float* b1   = (const float*)d_in[5];
    const float* w2   = (const float*)d_in[6];
    const float* b2   = (const float*)d_in[7];
    const float* wo   = (const float*)d_in[8];
    const float* bo   = (const float*)d_in[9];
    float* out = (float*)d_out;

    cudaFuncSetAttribute(proj_mma, cudaFuncAttributeMaxDynamicSharedMemorySize, PSMEM2);
    cudaFuncSetAttribute(gemm1_mma, cudaFuncAttributeMaxDynamicSharedMemorySize, SMEM_BYTES);
    cudaFuncSetAttribute(gemm2_mma, cudaFuncAttributeMaxDynamicSharedMemorySize, SMEM_BYTES);

    setup_kernel<<<385, 256>>>(mask, wo, w1, b1, w2, b2, ln_w, ln_b);
    proj_mma<<<256, 128, PSMEM2>>>(m, mask);

    dim3 g1(64, 64);
    gemm1_mma<<<g1, 256, SMEM_BYTES>>>();
    gemm2_mma<<<512, 256, SMEM_BYTES>>>(bo, out);
}

// round 14
// speedup vs baseline: 1.0744x; 1.0323x over previous
#include <cuda_runtime.h>
#include <cstdint>

#define S_DIM 128
#define N_DIM 256
#define CM 256
#define CH 32
#define CZ 128
#define P_DIM 8192
#define LN_EPS 1e-5f
#define OPM_EPS 1e-3f

__device__ __align__(16) float g_a[P_DIM * S_DIM];
__device__ __align__(16) float g_b[P_DIM * S_DIM];
__device__ __align__(16) float g_O[(size_t)P_DIM * P_DIM];
__device__ __align__(16) float g_woT[CZ * CH * CH];
__device__ __align__(16) float g_wpT[64 * CM];
__device__ float g_cw[64];
__device__ float g_c2[64];
__device__ float g_norm[N_DIM * N_DIM];

__device__ __forceinline__ uint32_t rna_tf32(float x) {
    uint32_t r;
    asm("cvt.rna.tf32.f32 %0, %1;" : "=r"(r) : "f"(x));
    return r;
}
__device__ __forceinline__ float rnaf(float x) { return __uint_as_float(rna_tf32(x)); }
__device__ __forceinline__ uint32_t smem_u32(const void* p) {
    uint32_t a;
    asm("{ .reg .u64 t; cvta.to.shared.u64 t, %1; cvt.u32.u64 %0, t; }" : "=r"(a) : "l"(p));
    return a;
}
__device__ __forceinline__ void mma_tf32(float* c, const uint32_t* a, const uint32_t* b) {
    asm volatile(
        "mma.sync.aligned.m16n8k8.row.col.f32.tf32.tf32.f32 "
        "{%0,%1,%2,%3}, {%4,%5,%6,%7}, {%8,%9}, {%0,%1,%2,%3};\n"
        : "+f"(c[0]), "+f"(c[1]), "+f"(c[2]), "+f"(c[3])
        : "r"(a[0]), "r"(a[1]), "r"(a[2]), "r"(a[3]), "r"(b[0]), "r"(b[1]));
}
__device__ __forceinline__ void ldsm_x4(uint32_t* r, uint32_t addr) {
    asm volatile("ldmatrix.sync.aligned.m8n8.x4.shared.b16 {%0,%1,%2,%3}, [%4];"
        : "=r"(r[0]), "=r"(r[1]), "=r"(r[2]), "=r"(r[3]) : "r"(addr));
}
__device__ __forceinline__ void cp16(uint32_t d, const float* s) {
    asm volatile("cp.async.cg.shared.global [%0], [%1], 16;" :: "r"(d), "l"(s));
}
__device__ __forceinline__ void cp16_ca(uint32_t d, const float* s) {
    asm volatile("cp.async.ca.shared.global [%0], [%1], 16;" :: "r"(d), "l"(s));
}
#define CP_COMMIT() asm volatile("cp.async.commit_group;" ::: "memory")
#define CP_WAIT1()  asm volatile("cp.async.wait_group 1;" ::: "memory")

// mbarrier helpers (sm_80+ baseline, assembles through compute_103)
#define MBAR_INIT(a, n) asm volatile("mbarrier.init.shared.b64 [%0], %1;" :: "r"(a), "r"(n) : "memory")
#define MBAR_ARRIVE(a)  asm volatile("mbarrier.arrive.shared.b64 _, [%0];" :: "r"(a) : "memory")
#define CPA_ARRIVE(a)   asm volatile("cp.async.mbarrier.arrive.noinc.shared.b64 [%0];" :: "r"(a) : "memory")
#define MBAR_WAIT(a, ph) do { \
    uint32_t _m = (a), _p = (ph), _d; \
    asm volatile("{ .reg .pred p; mbarrier.try_wait.parity.acquire.cta.shared::cta.b64 p, [%1], %2; selp.b32 %0,1,0,p; }" \
        : "=r"(_d) : "r"(_m), "r"(_p) : "memory"); \
    if (!_d) { \
        asm volatile("{ .reg .pred P1; WL_%=: mbarrier.try_wait.parity.acquire.cta.shared::cta.b64 P1, [%0], %1, 0x989680; @P1 bra.uni WD_%=; bra.uni WL_%=; WD_%=: }" \
            :: "r"(_m), "r"(_p) : "memory"); \
    } } while (0)

#define ROW_BYTES   144u
#define STAGE_BYTES 36864u
#define B_OFF       18432u
#define SMEM_BYTES  (3 * 36864)
#define GSMEM2      (3 * 36864 + 64)
#define PSTG_FL     6912
#define PB_FL       4608
#define PSMEM2      (2 * 27648 + 1024)

__device__ __forceinline__ void mma_chunk(uint32_t a_base, uint32_t b_base,
                                          float acc[4][4][4]) {
    #pragma unroll
    for (int kk = 0; kk < 4; kk++) {
        uint32_t af[4][4], bf[4][2];
        #pragma unroll
        for (int mt = 0; mt < 4; mt++)
            ldsm_x4(af[mt], a_base + kk * 32 + mt * (16 * ROW_BYTES));
        #pragma unroll
        for (int pr = 0; pr < 2; pr++) {
            uint32_t t[4];
            ldsm_x4(t, b_base + kk * 32 + pr * (16 * ROW_BYTES));
            bf[2 * pr][0] = t[0]; bf[2 * pr][1] = t[1];
            bf[2 * pr + 1][0] = t[2]; bf[2 * pr + 1][1] = t[3];
        }
        #pragma unroll
        for (int mt = 0; mt < 4; mt++)
            #pragma unroll
            for (int nt = 0; nt < 4; nt++)
                mma_tf32(acc[mt][nt], af[mt], bf[nt]);
    }
}

// ============================================================================
// setup kernel: block 0 = prep; blocks 1..256 = norm; 257..384 = woT transpose
// ============================================================================
__global__ void __launch_bounds__(256) setup_kernel(
        const float* __restrict__ mask,
        const float* __restrict__ wo,
        const float* __restrict__ w1, const float* __restrict__ b1,
        const float* __restrict__ w2, const float* __restrict__ b2,
        const float* __restrict__ ln_w, const float* __restrict__ ln_b) {
    const int bid = blockIdx.x;
    if (bid == 0) {
        const int h = threadIdx.x & 63, kq = threadIdx.x >> 6;
        const float* w = (h < 32) ? w1 : w2;
        const int hh = h & 31;
        float cw = 0.f, cb = 0.f;
        for (int k = kq * 64; k < kq * 64 + 64; k++) {
            float v = ln_w[k] * w[k * CH + hh];
            float rv = rnaf(v);
            g_wpT[h * CM + k] = rv;
            cw += rv;
            cb += ln_b[k] * w[k * CH + hh];
        }
        __shared__ float scw[4][64], scb[4][64];
        scw[kq][h] = cw; scb[kq][h] = cb;
        __syncthreads();
        if (kq == 0) {
            g_cw[h] = scw[0][h] + scw[1][h] + scw[2][h] + scw[3][h];
            float tb = scb[0][h] + scb[1][h] + scb[2][h] + scb[3][h];
            g_c2[h] = tb + ((h < 32) ? b1[h] : b2[hh]);
        }
    } else if (bid <= 256) {
        const int i = bid - 1, j = threadIdx.x;
        __shared__ float mi[S_DIM];
        if (j < S_DIM) mi[j] = mask[j * N_DIM + i];
        __syncthreads();
        float acc = 0.f;
        #pragma unroll 8
        for (int s = 0; s < S_DIM; s++) acc += mi[s] * mask[s * N_DIM + j];
        g_norm[i * N_DIM + j] = acc + OPM_EPS;
    } else {
        const int t = bid - 257;
        __shared__ float tt[32][33];
        const int kb = (t & 31) * 32, zb = (t >> 5) * 32;
        const int tx = threadIdx.x & 31, ty = threadIdx.x >> 5;
        #pragma unroll
        for (int r = 0; r < 32; r += 8)
            tt[ty + r][tx] = wo[(size_t)(kb + ty + r) * CZ + zb + tx];
        __syncthreads();
        #pragma unroll
        for (int r = 0; r < 32; r += 8)
            g_woT[(size_t)(zb + ty + r) * 1024 + kb + tx] = rnaf(tt[tx][ty + r]);
    }
}

// ============================================================================
// proj_mma: rna(m) @ W' per n-CTA, LayerNorm stats inline (unchanged from R13)
// ============================================================================
__global__ void __launch_bounds__(128) proj_mma(const float* __restrict__ m,
                                                const float* __restrict__ mask) {
    extern __shared__ __align__(16) float sm[];
    float2* sstat = (float2*)&sm[2 * PSTG_FL];
    const uint32_t sbase = smem_u32(sm);
    const int tid = threadIdx.x, wid = tid >> 5, lane = tid & 31;
    const int wm = (wid & 1) * 64, wn = (wid >> 1) * 32;
    const int n = blockIdx.x;
    const int lg = lane >> 3, lrow = lane & 7;
    const uint32_t a_lo = (uint32_t)(wm + (lg & 1) * 8 + lrow) * ROW_BYTES
                        + (uint32_t)(lg >> 1) * 16;
    const uint32_t b_lo = PB_FL * 4u + (uint32_t)(wn + (lg >> 1) * 8 + lrow) * ROW_BYTES
                        + (uint32_t)(lg & 1) * 16;
    const int rbase = tid >> 3, cc = tid & 7;

    float acc[4][4][4];
    #pragma unroll
    for (int a = 0; a < 4; a++)
        #pragma unroll
        for (int b = 0; b < 4; b++)
            #pragma unroll
            for (int e = 0; e < 4; e++) acc[a][b][e] = 0.f;

    float4 pa[8], pb[4];
    float s1p[8], s2p[8];
    #pragma unroll
    for (int i = 0; i < 8; i++) { s1p[i] = 0.f; s2p[i] = 0.f; }

    auto load_regs = [&](int ch) {
        const int kb = ch * 32;
        #pragma unroll
        for (int i = 0; i < 8; i++) {
            const int rr = rbase + i * 16;
            pa[i] = *(const float4*)&m[((size_t)rr * N_DIM + n) * CM + kb + cc * 4];
            s1p[i] += pa[i].x + pa[i].y + pa[i].z + pa[i].w;
            s2p[i] += pa[i].x * pa[i].x + pa[i].y * pa[i].y
                    + pa[i].z * pa[i].z + pa[i].w * pa[i].w;
        }
        #pragma unroll
        for (int i = 0; i < 4; i++) {
            const int f = tid + i * 128, rr = f >> 3, c8 = f & 7;
            pb[i] = *(const float4*)&g_wpT[rr * CM + kb + c8 * 4];
        }
    };
    auto sts_regs = [&](int buf) {
        float* A = &sm[buf * PSTG_FL];
        float* B = A + PB_FL;
        #pragma unroll
        for (int i = 0; i < 8; i++) {
            const int rr = rbase + i * 16;
            float4 v;
            v.x = rnaf(pa[i].x); v.y = rnaf(pa[i].y);
            v.z = rnaf(pa[i].z); v.w = rnaf(pa[i].w);
            *(float4*)&A[rr * 36 + cc * 4] = v;
        }
        #pragma unroll
        for (int i = 0; i < 4; i++) {
            const int f = tid + i * 128, rr = f >> 3, c8 = f & 7;
            *(float4*)&B[rr * 36 + c8 * 4] = pb[i];
        }
    };

    load_regs(0);
    sts_regs(0);
    __syncthreads();

    #pragma unroll 1
    for (int ch = 0; ch < 8; ch++) {
        if (ch < 7) load_regs(ch + 1);
        const uint32_t so = sbase + (uint32_t)(ch & 1) * (PSTG_FL * 4u);
        mma_chunk(so + a_lo, so + b_lo, acc);
        if (ch < 7) {
            sts_regs((ch + 1) & 1);
            __syncthreads();
        }
    }

    #pragma unroll
    for (int i = 0; i < 8; i++) {
        float a = s1p[i], b = s2p[i];
        #pragma unroll
        for (int o = 1; o < 8; o <<= 1) {
            a += __shfl_xor_sync(0xffffffff, a, o);
            b += __shfl_xor_sync(0xffffffff, b, o);
        }
        if (cc == 0) {
            const int row = rbase + i * 16;
            float mu = a * (1.f / CM);
            float var = b * (1.f / CM) - mu * mu;
            float r = rsqrtf(var + LN_EPS);
            sstat[row] = make_float2(r, mu * r);
        }
    }
    __syncthreads();

    float* dst = (wn == 0) ? g_a : g_b;
    #pragma unroll
    for (int mt = 0; mt < 4; mt++) {
        const int s0 = wm + mt * 16 + (lane >> 2);
        const float2 st0 = sstat[s0];
        const float2 st1 = sstat[s0 + 8];
        const float mk0 = mask[s0 * N_DIM + n];
        const float mk1 = mask[(s0 + 8) * N_DIM + n];
        #pragma unroll
        for (int nt = 0; nt < 4; nt++) {
            const int h = wn + nt * 8 + (lane & 3) * 2;
            const int hh = h & 31;
            const float cwa = g_cw[h], cwb = g_cw[h + 1];
            const float c2a = g_c2[h], c2b = g_c2[h + 1];
            float* d0 = &dst[(size_t)(n * CH + hh) * S_DIM];
            float* d1 = d0 + S_DIM;
            d0[s0]     = rnaf((st0.x * acc[mt][nt][0] - st0.y * cwa + c2a) * mk0);
            d1[s0]     = rnaf((st0.x * acc[mt][nt][1] - st0.y * cwb + c2b) * mk0);
            d0[s0 + 8] = rnaf((st1.x * acc[mt][nt][2] - st1.y * cwa + c2a) * mk1);
            d1[s0 + 8] = rnaf((st1.x * acc[mt][nt][3] - st1.y * cwb + c2b) * mk1);
        }
    }
}

// ============================================================================
// GEMM1: unchanged (control arm, __syncthreads ring)
// ============================================================================
__global__ void __launch_bounds__(256, 2) gemm1_mma() {
    extern __shared__ __align__(16) float sm[];
    const uint32_t sbase = smem_u32(sm);
    const int tid = threadIdx.x, wid = tid >> 5, lane = tid & 31;
    const int wm = (wid & 1) * 64, wn = (wid >> 1) * 32;
    const int p0 = blockIdx.y * 128, q0 = blockIdx.x * 128;
    const int lg = lane >> 3, lrow = lane & 7;
    const uint32_t a_lo = (uint32_t)(wm + (lg & 1) * 8 + lrow) * ROW_BYTES
                        + (uint32_t)(lg >> 1) * 16;
    const uint32_t b_lo = B_OFF + (uint32_t)(wn + (lg >> 1) * 8 + lrow) * ROW_BYTES
                        + (uint32_t)(lg & 1) * 16;

    float acc[4][4][4];
    #pragma unroll
    for (int a = 0; a < 4; a++)
        #pragma unroll
        for (int b = 0; b < 4; b++)
            #pragma unroll
            for (int e = 0; e < 4; e++) acc[a][b][e] = 0.f;

    auto copy1 = [&](int ch, int st) {
        const int kb = ch * 32;
        const uint32_t dA = sbase + st * STAGE_BYTES;
        const uint32_t dB = dA + B_OFF;
        #pragma unroll
        for (int i = 0; i < 4; i++) {
            int f = tid + i * 256, rr = f >> 3, cc = f & 7;
            cp16(dA + rr * ROW_BYTES + cc * 16,
                 &g_a[(size_t)(p0 + rr) * S_DIM + kb + cc * 4]);
            cp16(dB + rr * ROW_BYTES + cc * 16,
                 &g_b[(size_t)(q0 + rr) * S_DIM + kb + cc * 4]);
        }
    };

    copy1(0, 0); CP_COMMIT();
    copy1(1, 1); CP_COMMIT();

    #pragma unroll
    for (int ch = 0; ch < 4; ch++) {
        CP_WAIT1();
        __syncthreads();
        const uint32_t so = sbase + (uint32_t)(ch % 3) * STAGE_BYTES;
        mma_chunk(so + a_lo, so + b_lo, acc);
        if (ch + 2 < 4) copy1(ch + 2, (ch + 2) % 3);
        CP_COMMIT();
    }

    #pragma unroll
    for (int mt = 0; mt < 4; mt++) {
        const int row0 = p0 + wm + mt * 16 + (lane >> 2);
        #pragma unroll
        for (int nt = 0; nt < 4; nt++) {
            const int col = q0 + wn + nt * 8 + (lane & 3) * 2;
            float2 v0, v1;
            v0.x = rnaf(acc[mt][nt][0]); v0.y = rnaf(acc[mt][nt][1]);
            v1.x = rnaf(acc[mt][nt][2]); v1.y = rnaf(acc[mt][nt][3]);
            *(float2*)&g_O[(size_t)row0 * P_DIM + col]       = v0;
            *(float2*)&g_O[(size_t)(row0 + 8) * P_DIM + col] = v1;
        }
    }
}

// ============================================================================
// GEMM2: per-warp mbarrier pipeline (experimental arm).
// 3-stage ring; full[s] via cp.async.mbarrier.arrive.noinc (count 256),
// empty[s] via mbarrier.arrive (count 256). No __syncthreads in mainloop ->
// warps de-phase, overlapping LDSM bursts with MMA bursts.
// ============================================================================
__global__ void __launch_bounds__(256, 2) gemm2_mma(const float* __restrict__ bo,
                                                    float* __restrict__ out) {
    extern __shared__ __align__(16) float sm[];
    const uint32_t sbase = smem_u32(sm);
    const uint32_t MB = sbase + 3 * STAGE_BYTES;   // full[s]=MB+16s, empty[s]=MB+16s+8
    const int tid = threadIdx.x, wid = tid >> 5, lane = tid & 31;
    const int wm = (wid & 1) * 64, wn = (wid >> 1) * 32;
    const int m0 = blockIdx.x * 128;
    const int i_idx = m0 >> 8, j0 = m0 & 255;
    const int lg = lane >> 3, lrow = lane & 7;
    const uint32_t a_lo = (uint32_t)(wm + (lg & 1) * 8 + lrow) * ROW_BYTES
                        + (uint32_t)(lg >> 1) * 16;
    const uint32_t b_lo = B_OFF + (uint32_t)(wn + (lg >> 1) * 8 + lrow) * ROW_BYTES
                        + (uint32_t)(lg & 1) * 16;

    if (tid == 0) {
        #pragma unroll
        for (int s = 0; s < 3; s++) {
            MBAR_INIT(MB + 16 * s, 256);
            MBAR_INIT(MB + 16 * s + 8, 256);
        }
    }
    __syncthreads();

    float acc[4][4][4];
    #pragma unroll
    for (int a = 0; a < 4; a++)
        #pragma unroll
        for (int b = 0; b < 4; b++)
            #pragma unroll
            for (int e = 0; e < 4; e++) acc[a][b][e] = 0.f;

    auto copy1 = [&](int ch, int st) {
        const float* gA = &g_O[((size_t)(i_idx * 32 + ch)) * P_DIM + (size_t)j0 * 32];
        const uint32_t dA = sbase + st * STAGE_BYTES;
        const uint32_t dB = dA + B_OFF;
        #pragma unroll
        for (int i = 0; i < 4; i++) {
            int f = tid + i * 256, rr = f >> 3, cc = f & 7;
            cp16(dA + rr * ROW_BYTES + cc * 16, &gA[f * 4]);
            cp16_ca(dB + rr * ROW_BYTES + cc * 16,
                    &g_woT[(size_t)rr * 1024 + ch * 32 + cc * 4]);
        }
    };

    int ps = 0, pp = 1, cs = 0, cph = 0;
    #pragma unroll
    for (int c = 0; c < 2; c++) {                 // prologue
        MBAR_WAIT(MB + 16 * ps + 8, pp);          // passes immediately (pp=1)
        copy1(c, ps);
        CPA_ARRIVE(MB + 16 * ps);
        if (++ps == 3) { ps = 0; pp ^= 1; }
    }

    #pragma unroll 1
    for (int ch = 0; ch < 32; ch++) {
        MBAR_WAIT(MB + 16 * cs, cph);             // stage full (acquire)
        const uint32_t so = sbase + (uint32_t)cs * STAGE_BYTES;
        mma_chunk(so + a_lo, so + b_lo, acc);
        MBAR_ARRIVE(MB + 16 * cs + 8);            // stage empty
        if (++cs == 3) { cs = 0; cph ^= 1; }
        if (ch + 2 < 32) {
            MBAR_WAIT(MB + 16 * ps + 8, pp);      // wait stage free
            copy1(ch + 2, ps);
            CPA_ARRIVE(MB + 16 * ps);
            if (++ps == 3) { ps = 0; pp ^= 1; }
        }
    }

    #pragma unroll
    for (int mt = 0; mt < 4; mt++) {
        const int row0 = m0 + wm + mt * 16 + (lane >> 2);
        const float inv0 = 1.0f / g_norm[row0];
        const float inv1 = 1.0f / g_norm[row0 + 8];
        #pragma unroll
        for (int nt = 0; nt < 4; nt++) {
            const int col = wn + nt * 8 + (lane & 3) * 2;
            const float b0v = bo[col], b1v = bo[col + 1];
            float2 v0, v1;
            v0.x = (acc[mt][nt][0] + b0v) * inv0;
            v0.y = (acc[mt][nt][1] + b1v) * inv0;
            v1.x = (acc[mt][nt][2] + b0v) * inv1;
            v1.y = (acc[mt][nt][3] + b1v) * inv1;
            *(float2*)&out[(size_t)row0 * CZ + col]       = v0;
            *(float2*)&out[(size_t)(row0 + 8) * CZ + col] = v1;
        }
    }
}

extern "C" void kernel_launch(void* const* d_in, const int* in_sizes, int n_in,
                              void* d_out, int out_size) {
    const float* m    = (const float*)d_in[0];
    const float* mask = (const float*)d_in[1];
    const float* ln_w = (const float*)d_in[2];
    const float* ln_b = (const float*)d_in[3];
    const float* w1   = (const float*)d_in[4];
    const float* b1   = (const float*)d_in[5];
    const float* w2   = (const float*)d_in[6];
    const float* b2   = (const float*)d_in[7];
    const float* wo   = (const float*)d_in[8];
    const float* bo   = (const float*)d_in[9];
    float* out = (float*)d_out;

    cudaFuncSetAttribute(proj_mma, cudaFuncAttributeMaxDynamicSharedMemorySize, PSMEM2);
    cudaFuncSetAttribute(gemm1_mma, cudaFuncAttributeMaxDynamicSharedMemorySize, SMEM_BYTES);
    cudaFuncSetAttribute(gemm2_mma, cudaFuncAttributeMaxDynamicSharedMemorySize, GSMEM2);

    setup_kernel<<<385, 256>>>(mask, wo, w1, b1, w2, b2, ln_w, ln_b);
    proj_mma<<<256, 128, PSMEM2>>>(m, mask);

    dim3 g1(64, 64);
    gemm1_mma<<<g1, 256, SMEM_BYTES>>>();
    gemm2_mma<<<512, 256, GSMEM2>>>(bo, out);
}